// round 14
// baseline (speedup 1.0000x reference)
#include <cuda_runtime.h>
#include <cuda_fp16.h>
#include <cstdint>

// FlexAttention fwd (causal + ALiBi), B=2,H=16,S=2048,D=128 fp32.
// Round 13: R11 + 2-deep ldsm lookahead (same buffers, reload-after-use),
// boundary-fused K preloads, strength-reduced cp.async addressing.
//   S' = Q' K^T          (Q pre-scaled by log2e/sqrt(D))
//   P = 2^(S' + bias'),  bias' = slope*log2e*(kv-q);  mask: bias'>0 -> 0
//   O += P V             (fp16 P/V, fp32 accum across all kv tiles)
//   epilogue: O /= rowsum(P)

#define B_  2
#define H_  16
#define S_  2048
#define D_  128
#define BQ  64
#define BK  64
#define NT  128
#define NELEM (B_*H_*S_*D_)

__device__ __half g_Kf[NELEM];
__device__ __half g_VTf[NELEM];  // transposed: [b,h,d,s]

// ---------------- helpers ----------------
__device__ __forceinline__ uint32_t smem_u32(const void* p) {
    uint32_t a;
    asm("{ .reg .u64 t; cvta.to.shared.u64 t, %1; cvt.u32.u64 %0, t; }"
        : "=r"(a) : "l"(p));
    return a;
}

__device__ __forceinline__ void cp16(uint32_t dst, const void* src) {
    asm volatile("cp.async.cg.shared.global [%0], [%1], 16;"
                 :: "r"(dst), "l"(src));
}
#define CP_COMMIT() asm volatile("cp.async.commit_group;")
#define CP_WAIT(n)  asm volatile("cp.async.wait_group %0;" :: "n"(n))

__device__ __forceinline__ void ldsm4(uint32_t& r0, uint32_t& r1,
                                      uint32_t& r2, uint32_t& r3, uint32_t a) {
    asm volatile("ldmatrix.sync.aligned.m8n8.x4.shared.b16 {%0,%1,%2,%3}, [%4];"
                 : "=r"(r0), "=r"(r1), "=r"(r2), "=r"(r3) : "r"(a));
}

// non-volatile: scheduled by dataflow
__device__ __forceinline__ void mma16816(float* c,
                                         uint32_t a0, uint32_t a1, uint32_t a2, uint32_t a3,
                                         uint32_t b0, uint32_t b1) {
    asm("mma.sync.aligned.m16n8k16.row.col.f32.f16.f16.f32 "
        "{%0,%1,%2,%3}, {%4,%5,%6,%7}, {%8,%9}, {%0,%1,%2,%3};"
        : "+f"(c[0]), "+f"(c[1]), "+f"(c[2]), "+f"(c[3])
        : "r"(a0), "r"(a1), "r"(a2), "r"(a3), "r"(b0), "r"(b1));
}

__device__ __forceinline__ float ex2(float x) {
    float r;
    asm("ex2.approx.ftz.f32 %0, %1;" : "=f"(r) : "f"(x));
    return r;
}

__device__ __forceinline__ uint32_t pack_h2(float a, float b) {
    __half2 v = __floats2half2_rn(a, b);
    return *(uint32_t*)&v;
}

// ---------------- preprocessing: K convert + V transpose ----------------
// grid (8192, 3): y=0/1 -> K convert halves, y=2 -> V transpose (exact 8192).
__global__ void prep_kernel(const float* __restrict__ k, const float* __restrict__ v) {
    const int sel = blockIdx.y;
    if (sel < 2) {
        int i = (((sel * 8192 + blockIdx.x) * 256) + threadIdx.x) * 4;
        float4 f = *(const float4*)(k + i);
        *(__half2*)(g_Kf + i)     = __floats2half2_rn(f.x, f.y);
        *(__half2*)(g_Kf + i + 2) = __floats2half2_rn(f.z, f.w);
    } else {
        __shared__ float t[32][33];
        int bx = blockIdx.x;                  // 0..8191 exactly
        int bh = bx >> 8;                     // 0..31
        int d0 = ((bx >> 6) & 3) * 32;        // 0..96
        int s0 = (bx & 63) * 32;              // 0..2016
        int tx = threadIdx.x & 31, ty = threadIdx.x >> 5;
        const float* src = v + (size_t)bh * S_ * D_;
#pragma unroll
        for (int kk = 0; kk < 4; kk++)
            t[ty + 8 * kk][tx] = src[(size_t)(s0 + ty + 8 * kk) * D_ + d0 + tx];
        __syncthreads();
#pragma unroll
        for (int kk = 0; kk < 4; kk++) {
            int d = d0 + ty + 8 * kk, s = s0 + tx;
            g_VTf[(size_t)(bh * D_ + d) * S_ + s] = __float2half_rn(t[tx][ty + 8 * kk]);
        }
    }
}

// ---------------- main kernel ----------------
// smem per CTA: Q 16KB, 2 stages of {K 16KB, VT 16KB} = 80KB. 2 CTAs/SM.
#define SM_Q    0
#define SM_STG  16384
#define STG_SZ  32768
#define OFF_K   0
#define OFF_V   16384
#define SM_TOTAL (SM_STG + 2 * STG_SZ)   // 81920

#define QSC (0.08838834764831845f * 1.4426950408889634f)   // log2e/sqrt(D)

__global__ __launch_bounds__(NT, 2)
void flex_attn_f16(float* __restrict__ O, const float* __restrict__ Q32) {
    extern __shared__ char smem[];
    const uint32_t sb = smem_u32(smem);
    const int tid = threadIdx.x, wid = tid >> 5, lane = tid & 31;

    // globally big-first (LPT): first 32 CTAs are the 32-tile jobs, etc.
    const int r = (int)blockIdx.x + 32 * (int)blockIdx.y;
    const int qt = 31 - (r >> 5);
    const int bh = r & 31;
    const int h = bh & 15;

    const int q0 = qt * BQ;
    const int nkt = qt + 1;
    const float spL = exp2f(-0.5f * (float)(h + 1)) * 1.4426950408889634f;
    const float sp8 = 8.0f * spL;

    const __half* gk = g_Kf + (size_t)bh * S_ * D_;
    const __half* gvt = g_VTf + (size_t)bh * D_ * S_;

    // ---- strength-reduced cp.async addressing (offsets affine in i) ----
    const int rr0 = tid >> 4, gg0 = tid & 15;
    const uint32_t offK0 = rr0 * 256 + (((uint32_t)(gg0 ^ (rr0 & 7))) << 4);
    const int r20 = tid >> 3, g20 = tid & 7;
    const uint32_t offV0 = r20 * 128 + (((uint32_t)(g20 ^ (r20 & 7))) << 4);
    const __half* kp0 = gk + rr0 * 128 + gg0 * 8;
    const __half* vp0 = gvt + (size_t)r20 * S_ + g20 * 8;

    // ---- issue stage 0 K/V (one cp.async group) ----
    {
        uint32_t ok = sb + SM_STG + OFF_K + offK0;
        uint32_t ov = sb + SM_STG + OFF_V + offV0;
        const __half* kq = kp0;
        const __half* vq = vp0;
#pragma unroll
        for (int i = 0; i < 8; i++) {
            cp16(ok, kq);
            cp16(ov, vq);
            ok += 2048; ov += 2048;
            kq += 1024; vq += 16 * S_;
        }
    }
    CP_COMMIT();

    // ---- Q tile: LDG fp32 -> cvt(prescale) -> STS fp16 swizzled ----
    {
        const float* gq32 = Q32 + (size_t)(bh * S_ + q0) * D_;
#pragma unroll
        for (int i = 0; i < 8; i++) {
            int idx = tid + i * NT;           // 0..1023 (64 rows x 16 chunks)
            int r2 = idx >> 4, g = idx & 15;
            const float4* p = (const float4*)(gq32 + r2 * 128 + g * 8);
            float4 f0 = p[0], f1 = p[1];
            uint32_t off = r2 * 256 + (((uint32_t)(g ^ (r2 & 7))) << 4);
            uint4 w;
            w.x = pack_h2(f0.x * QSC, f0.y * QSC);
            w.y = pack_h2(f0.z * QSC, f0.w * QSC);
            w.z = pack_h2(f1.x * QSC, f1.y * QSC);
            w.w = pack_h2(f1.z * QSC, f1.w * QSC);
            *(uint4*)(smem + SM_Q + off) = w;
        }
    }

    // ---- per-lane fragment addressing ----
    const int ch = lane >> 3, sw3 = lane & 7;
    const int arow = 16 * wid + sw3 + (ch & 1) * 8;
    const int agsel = ch >> 1;
    const int brow_l = sw3 + (ch >> 1) * 8;
    const int bgsel = ch & 1;

    const int rq = lane >> 2;
    const int cw = 2 * (lane & 3);
    const int qi0 = q0 + 16 * wid + rq;
    const int qi1 = qi0 + 8;

    CP_WAIT(0);
    __syncthreads();

    uint32_t Qf[8][4];
#pragma unroll
    for (int k = 0; k < 8; k++) {
        uint32_t aoff = (uint32_t)(arow * 256) +
                        (((uint32_t)((2 * k + agsel) ^ sw3)) << 4);
        ldsm4(Qf[k][0], Qf[k][1], Qf[k][2], Qf[k][3], sb + SM_Q + aoff);
    }

    float Of[16][4];
#pragma unroll
    for (int j = 0; j < 16; j++)
#pragma unroll
        for (int t = 0; t < 4; t++) Of[j][t] = 0.0f;
    float l0 = 0.0f, l1 = 0.0f;

    for (int kt = 0; kt < nkt; kt++) {
        const uint32_t st = sb + SM_STG + (kt & 1) * STG_SZ;
        const bool has_next = (kt + 1 < nkt);

        if (has_next) {
            const uint32_t sn = sb + SM_STG + ((kt + 1) & 1) * STG_SZ;
            const int kv0 = (kt + 1) * BK;
            uint32_t ok = sn + OFF_K + offK0;
            uint32_t ov = sn + OFF_V + offV0;
            const __half* kq = kp0 + (size_t)kv0 * D_;
            const __half* vq = vp0 + kv0;
#pragma unroll
            for (int i = 0; i < 8; i++) {
                cp16(ok, kq);
                cp16(ov, vq);
                ok += 2048; ov += 2048;
                kq += 1024; vq += 16 * S_;
            }
            CP_COMMIT();
        }

        {
            // K-frag loader for one 32-col half: 2 ldsm4 at reduction step k
            auto ldB1h = [&](uint32_t* bb, int k, int prb) {
#pragma unroll
                for (int pr = 0; pr < 2; pr++) {
                    int n = (prb + pr) * 16 + brow_l;
                    uint32_t boff = (uint32_t)(n * 256) +
                                    (((uint32_t)((2 * k + bgsel) ^ sw3)) << 4);
                    ldsm4(bb[4 * pr], bb[4 * pr + 1], bb[4 * pr + 2], bb[4 * pr + 3],
                          st + OFF_K + boff);
                }
            };
            // VT-frag loader: group g = (kv 16-blk g>>1, d-half g&1)
            auto ldB2 = [&](uint32_t* vb, int g) {
                int kk = g >> 1;
#pragma unroll
                for (int i = 0; i < 4; i++) {
                    int pr2 = 4 * (g & 1) + i;
                    int n = pr2 * 16 + brow_l;
                    uint32_t voff = (uint32_t)(n * 128) +
                                    (((uint32_t)((2 * kk + bgsel) ^ sw3)) << 4);
                    ldsm4(vb[4 * i], vb[4 * i + 1], vb[4 * i + 2], vb[4 * i + 3],
                          st + OFF_V + voff);
                }
            };
            auto smax = [&](float (*Sh)[4], int jbase, uint32_t* ph) {
                float bj = spL * (float)(kt * BK + 8 * jbase + cw - qi0);
#pragma unroll
                for (int j = 0; j < 4; j++) {
                    float b00 = bj, b01 = bj + spL;
                    float b10 = bj - sp8, b11 = b01 - sp8;
                    float e00 = (b00 > 0.0f) ? 0.0f : ex2(Sh[j][0] + b00);
                    float e01 = (b01 > 0.0f) ? 0.0f : ex2(Sh[j][1] + b01);
                    float e10 = (b10 > 0.0f) ? 0.0f : ex2(Sh[j][2] + b10);
                    float e11 = (b11 > 0.0f) ? 0.0f : ex2(Sh[j][3] + b11);
                    l0 += e00 + e01;
                    l1 += e10 + e11;
                    ph[2 * j]     = pack_h2(e00, e01);
                    ph[2 * j + 1] = pack_h2(e10, e11);
                    bj += sp8;
                }
            };

            float Sa[4][4], Sb[4][4];
#pragma unroll
            for (int j = 0; j < 4; j++)
#pragma unroll
                for (int t = 0; t < 4; t++) { Sa[j][t] = 0.0f; Sb[j][t] = 0.0f; }

            // ---- GEMM1-A: S cols 0-31, 2-deep K pipeline ----
            uint32_t kA[8], kB[8];
            ldB1h(kA, 0, 0);
            ldB1h(kB, 1, 0);
#pragma unroll
            for (int k = 0; k < 8; k++) {
                uint32_t* cur = (k & 1) ? kB : kA;
                mma16816(Sa[0], Qf[k][0], Qf[k][1], Qf[k][2], Qf[k][3], cur[0], cur[1]);
                mma16816(Sa[1], Qf[k][0], Qf[k][1], Qf[k][2], Qf[k][3], cur[2], cur[3]);
                mma16816(Sa[2], Qf[k][0], Qf[k][1], Qf[k][2], Qf[k][3], cur[4], cur[5]);
                mma16816(Sa[3], Qf[k][0], Qf[k][1], Qf[k][2], Qf[k][3], cur[6], cur[7]);
                // reload the just-consumed buffer: k+2 of half A, or k-6 of half B
                if (k < 6) ldB1h(cur, k + 2, 0);
                else       ldB1h(cur, k - 6, 2);   // boundary fusion into GEMM1-B
            }

            // ---- GEMM1-B: S cols 32-63, pipeline already primed ----
#pragma unroll
            for (int k = 0; k < 8; k++) {
                uint32_t* cur = (k & 1) ? kB : kA;
                mma16816(Sb[0], Qf[k][0], Qf[k][1], Qf[k][2], Qf[k][3], cur[0], cur[1]);
                mma16816(Sb[1], Qf[k][0], Qf[k][1], Qf[k][2], Qf[k][3], cur[2], cur[3]);
                mma16816(Sb[2], Qf[k][0], Qf[k][1], Qf[k][2], Qf[k][3], cur[4], cur[5]);
                mma16816(Sb[3], Qf[k][0], Qf[k][1], Qf[k][2], Qf[k][3], cur[6], cur[7]);
                if (k < 6) ldB1h(cur, k + 2, 2);
            }

            // prime V pipeline 2 deep; softmax-A covers the latency
            uint32_t vA[16], vB[16];
            ldB2(vA, 0);
            ldB2(vB, 1);

            uint32_t phA[8], phB[8];
            smax(Sa, 0, phA);

            // ---- GEMM2-A: groups 0-3, reload-after-use (g+2) ----
#pragma unroll
            for (int g = 0; g < 4; g++) {
                uint32_t* cur = (g & 1) ? vB : vA;
                int kk = g >> 1;
                uint32_t a0 = phA[4 * kk],     a1 = phA[4 * kk + 1],
                         a2 = phA[4 * kk + 2], a3 = phA[4 * kk + 3];
#pragma unroll
                for (int i = 0; i < 4; i++) {
                    int pr2 = 4 * (g & 1) + i;
                    mma16816(Of[2 * pr2],     a0, a1, a2, a3, cur[4 * i], cur[4 * i + 1]);
                    mma16816(Of[2 * pr2 + 1], a0, a1, a2, a3, cur[4 * i + 2], cur[4 * i + 3]);
                }
                ldB2(cur, g + 2);                 // g+2 <= 5 here
            }

            smax(Sb, 4, phB);

            // ---- GEMM2-B: groups 4-7 ----
#pragma unroll
            for (int g = 4; g < 8; g++) {
                uint32_t* cur = (g & 1) ? vB : vA;
                int kk2 = (g >> 1) & 1;
                uint32_t a0 = phB[4 * kk2],     a1 = phB[4 * kk2 + 1],
                         a2 = phB[4 * kk2 + 2], a3 = phB[4 * kk2 + 3];
#pragma unroll
                for (int i = 0; i < 4; i++) {
                    int pr2 = 4 * (g & 1) + i;
                    mma16816(Of[2 * pr2],     a0, a1, a2, a3, cur[4 * i], cur[4 * i + 1]);
                    mma16816(Of[2 * pr2 + 1], a0, a1, a2, a3, cur[4 * i + 2], cur[4 * i + 3]);
                }
                if (g < 6) ldB2(cur, g + 2);
            }
        }

        if (has_next) {
            CP_WAIT(0);
            __syncthreads();
        }
    }

    // ---- epilogue ----
#pragma unroll
    for (int off = 1; off < 4; off <<= 1) {
        l0 += __shfl_xor_sync(0xffffffffu, l0, off);
        l1 += __shfl_xor_sync(0xffffffffu, l1, off);
    }
    float i0 = 1.0f / l0, i1 = 1.0f / l1;

    float* o0 = O + (size_t)(bh * S_ + qi0) * D_;
    float* o1 = O + (size_t)(bh * S_ + qi1) * D_;
#pragma unroll
    for (int j = 0; j < 16; j++) {
        int c = 8 * j + cw;
        float2 v0 = make_float2(Of[j][0] * i0, Of[j][1] * i0);
        float2 v1 = make_float2(Of[j][2] * i1, Of[j][3] * i1);
        *(float2*)(o0 + c) = v0;
        *(float2*)(o1 + c) = v1;
    }
}

// ---------------- launch ----------------
extern "C" void kernel_launch(void* const* d_in, const int* in_sizes, int n_in,
                              void* d_out, int out_size) {
    const float* q = (const float*)d_in[0];
    const float* k = (const float*)d_in[1];
    const float* v = (const float*)d_in[2];
    float* o = (float*)d_out;
    (void)in_sizes; (void)n_in; (void)out_size;

    cudaFuncSetAttribute(flex_attn_f16,
                         cudaFuncAttributeMaxDynamicSharedMemorySize, SM_TOTAL);

    prep_kernel<<<dim3(8192, 3), 256>>>(k, v);
    flex_attn_f16<<<dim3(32, 32, 1), NT, SM_TOTAL>>>(o, q);
}